// round 2
// baseline (speedup 1.0000x reference)
#include <cuda_runtime.h>

// VectorQuantizer: z[N,64] fp32, codebook[1024,64] fp32
// outputs (flattened fp32): z_q_st[N*64], vq_loss[1], idx[N], perplexity[1]

#define N_CODES 1024
#define DIM     64
#define TPB     256
#define CHUNK   128

__device__ double g_sumsq;
__device__ int    g_hist[N_CODES];
__device__ float  g_cc[N_CODES];

__device__ __forceinline__ unsigned long long pack2(float a, float b) {
    unsigned long long r;
    asm("mov.b64 %0, {%1, %2};" : "=l"(r) : "f"(a), "f"(b));
    return r;
}
__device__ __forceinline__ void fma2(unsigned long long& acc,
                                     unsigned long long a, unsigned long long b) {
    asm("fma.rn.f32x2 %0, %1, %2, %0;" : "+l"(acc) : "l"(a), "l"(b));
}
__device__ __forceinline__ float2 unpack2(unsigned long long v) {
    float2 f;
    asm("mov.b64 {%0, %1}, %2;" : "=f"(f.x), "=f"(f.y) : "l"(v));
    return f;
}

// Simulate XLA:GPU's warp row-reduction of sum(x*x) over 64 contiguous f32:
//   one warp per row, 2-wide vectorized contiguous reads:
//     leaf_t = fl(x[2t]^2 + x[2t+1]^2),  t = 0..31   (mul then add, NO fma)
//   then shfl-down butterfly: for o in {16,8,4,2,1}: a[t] = fl(a[t] + a[t+o])
__device__ __forceinline__ float xla_row_sumsq(const float4* row) {
    float a[32];
#pragma unroll
    for (int j = 0; j < 16; j++) {
        float4 v = row[j];
        a[2 * j]     = __fadd_rn(__fmul_rn(v.x, v.x), __fmul_rn(v.y, v.y));
        a[2 * j + 1] = __fadd_rn(__fmul_rn(v.z, v.z), __fmul_rn(v.w, v.w));
    }
#pragma unroll
    for (int o = 16; o >= 1; o >>= 1)
#pragma unroll
        for (int t = 0; t < 16; t++)
            if (t < o) a[t] = __fadd_rn(a[t], a[t + o]);
    return a[0];
}

// Zero accumulators + per-code squared norms with the SAME reduction tree.
__global__ void vq_init_kernel(const float* __restrict__ cb) {
    int i = blockIdx.x * blockDim.x + threadIdx.x;
    if (i < N_CODES) {
        g_hist[i] = 0;
        g_cc[i] = xla_row_sumsq((const float4*)(cb + (size_t)i * DIM));
    }
    if (i == 0) g_sumsq = 0.0;
}

__global__ __launch_bounds__(TPB) void vq_main_kernel(
    const float* __restrict__ z, const float* __restrict__ cb,
    float* __restrict__ out, int N)
{
    __shared__ __align__(16) float s_cb[CHUNK * DIM];   // 32 KB
    __shared__ float  s_cc[CHUNK];
    __shared__ double s_red[TPB];

    const int token = blockIdx.x * TPB + threadIdx.x;
    const int tok   = (token < N) ? token : (N - 1);    // clamp (N % TPB == 0 in practice)

    // Load this thread's z row, pack into f32x2 operands, compute zz via the
    // XLA-matched warp-tree reduction.
    unsigned long long zp[DIM / 2];
    float zz;
    {
        const float4* zr = (const float4*)(z + (size_t)tok * DIM);
        float4 v[16];
#pragma unroll
        for (int j = 0; j < 16; j++) {
            v[j] = zr[j];
            zp[2 * j]     = pack2(v[j].x, v[j].y);
            zp[2 * j + 1] = pack2(v[j].z, v[j].w);
        }
        float a[32];
#pragma unroll
        for (int j = 0; j < 16; j++) {
            a[2 * j]     = __fadd_rn(__fmul_rn(v[j].x, v[j].x), __fmul_rn(v[j].y, v[j].y));
            a[2 * j + 1] = __fadd_rn(__fmul_rn(v[j].z, v[j].z), __fmul_rn(v[j].w, v[j].w));
        }
#pragma unroll
        for (int o = 16; o >= 1; o >>= 1)
#pragma unroll
            for (int t = 0; t < 16; t++)
                if (t < o) a[t] = __fadd_rn(a[t], a[t + o]);
        zz = a[0];
    }

    float bestd = 3.402823466e+38f;
    int   best  = 0;

    for (int base = 0; base < N_CODES; base += CHUNK) {
        __syncthreads();
        {   // cooperative coalesced load of the codebook chunk
            const float4* src = (const float4*)(cb + (size_t)base * DIM);
            float4* dst = (float4*)s_cb;
            for (int j = threadIdx.x; j < CHUNK * DIM / 4; j += TPB)
                dst[j] = src[j];
            if (threadIdx.x < CHUNK) s_cc[threadIdx.x] = g_cc[base + threadIdx.x];
        }
        __syncthreads();

#pragma unroll 1
        for (int c = 0; c < CHUNK; c++) {
            const ulonglong2* crow = (const ulonglong2*)(s_cb + c * DIM);
            unsigned long long a0 = 0ull, a1 = 0ull;   // packed (0.f, 0.f)
#pragma unroll
            for (int j = 0; j < 16; j++) {
                ulonglong2 b = crow[j];                 // broadcast LDS.128
                fma2(a0, zp[2 * j],     b.x);
                fma2(a1, zp[2 * j + 1], b.y);
            }
            float2 f0 = unpack2(a0), f1 = unpack2(a1);
            float dot = __fadd_rn(__fadd_rn(f0.x, f0.y), __fadd_rn(f1.x, f1.y));
            // d = fl( fl(zz + cc) - 2*dot )   (2*dot is exact)
            float t = __fadd_rn(zz, s_cc[c]);
            float d = __fsub_rn(t, __fmul_rn(2.0f, dot));
            if (d < bestd) { bestd = d; best = base + c; }
        }
    }

    // ---- epilogue: idx, gather + straight-through output, loss partial ----
    double ssum = 0.0;
    if (token < N) {
        out[(size_t)N * DIM + 1 + token] = (float)best;
        const float4* q  = (const float4*)(cb + (size_t)best * DIM);
        const float4* zr = (const float4*)(z + (size_t)token * DIM);
        float4* o = (float4*)(out + (size_t)token * DIM);
#pragma unroll
        for (int j = 0; j < 16; j++) {
            float4 qv = q[j];
            float4 zv = zr[j];
            float d0 = __fsub_rn(qv.x, zv.x);
            float d1 = __fsub_rn(qv.y, zv.y);
            float d2 = __fsub_rn(qv.z, zv.z);
            float d3 = __fsub_rn(qv.w, zv.w);
            float4 ov;
            ov.x = __fadd_rn(zv.x, d0);   // z + sg(z_q - z), fp32-faithful
            ov.y = __fadd_rn(zv.y, d1);
            ov.z = __fadd_rn(zv.z, d2);
            ov.w = __fadd_rn(zv.w, d3);
            o[j] = ov;
            ssum += (double)__fmul_rn(d0, d0);
            ssum += (double)__fmul_rn(d1, d1);
            ssum += (double)__fmul_rn(d2, d2);
            ssum += (double)__fmul_rn(d3, d3);
        }
        atomicAdd(&g_hist[best], 1);
    }

    s_red[threadIdx.x] = ssum;
    __syncthreads();
    for (int s = TPB / 2; s > 0; s >>= 1) {
        if (threadIdx.x < s) s_red[threadIdx.x] += s_red[threadIdx.x + s];
        __syncthreads();
    }
    if (threadIdx.x == 0) atomicAdd(&g_sumsq, s_red[0]);
}

__global__ void vq_finalize_kernel(float* __restrict__ out, int N) {
    __shared__ double s_red[N_CODES];
    int i = threadIdx.x;
    float e    = __fdiv_rn((float)g_hist[i], (float)N);
    float term = __fmul_rn(e, logf(__fadd_rn(e, 1e-10f)));
    s_red[i] = (double)term;
    __syncthreads();
    for (int s = N_CODES / 2; s > 0; s >>= 1) {
        if (i < s) s_red[i] += s_red[i + s];
        __syncthreads();
    }
    if (i == 0) {
        float usage = -(float)s_red[0];
        float m  = (float)(g_sumsq / (double)((size_t)N * DIM));
        float vq = __fadd_rn(m, __fmul_rn(0.4f, m));          // mean1 + BETA*mean2
        vq = __fadd_rn(vq, __fmul_rn(0.01f, usage));          // + 0.01*usage_loss
        out[(size_t)N * DIM]         = vq;                     // vq_loss
        out[(size_t)N * DIM + 1 + N] = expf(usage);            // perplexity
    }
}

extern "C" void kernel_launch(void* const* d_in, const int* in_sizes, int n_in,
                              void* d_out, int out_size) {
    const float* z  = (const float*)d_in[0];
    const float* cb = (const float*)d_in[1];
    float* out = (float*)d_out;
    int N = in_sizes[0] / DIM;   // 131072

    vq_init_kernel<<<(N_CODES + 255) / 256, 256>>>(cb);
    vq_main_kernel<<<(N + TPB - 1) / TPB, TPB>>>(z, cb, out, N);
    vq_finalize_kernel<<<1, N_CODES>>>(out, N);
}